// round 12
// baseline (speedup 1.0000x reference)
#include <cuda_runtime.h>

// Per row z (Z=200000):
//   out[0:48]      = NORM * x2[z,0]   * (x1[z,:] @ w00)   w00 = weights[z,:2304] as 48x48
//   out[48+6p+...] = NORM * x2[z,1+j] * (x1[z,:] @ w01)   w01 = weights[z,2304:] as 48x10
// NORM = 1/sqrt(48).
//
// R8: R4 structure (role-pure warps, float4/float2 __ldcs weights, direct
// __stcs stores) wrapped in a persistent grid-stride loop (grid ~= 6
// blocks/SM) to remove ~13 wave transitions + tail imbalance.

#define NS   48
#define NV   10
#define WPR  2784
#define OPR  78
#define NORM 0.14433756729740643f

#define RPB  16
#define TPB  288
#define PERSISTENT_BLOCKS 912   // ~6 per SM on 152 SMs

__global__ __launch_bounds__(TPB, 6)
void tpfirst_kernel(const float* __restrict__ x1,
                    const float* __restrict__ x2,
                    const float* __restrict__ W,
                    float* __restrict__ out,
                    int Z, int ntiles)
{
    __shared__ float x1s[RPB * NS];
    __shared__ float x2s[RPB * 4];

    const int t = threadIdx.x;

    for (int tile = blockIdx.x; tile < ntiles; tile += gridDim.x) {
        const int z0 = tile * RPB;

        // cooperative staging (all 288 threads)
        #pragma unroll
        for (int i = t; i < RPB * NS; i += TPB) {
            int zz = z0 + i / NS;
            x1s[i] = (zz < Z) ? x1[(size_t)zz * NS + (i % NS)] : 0.f;
        }
        if (t < RPB * 4) {
            int zz = z0 + (t >> 2);
            x2s[t] = (zz < Z) ? x2[(size_t)zz * 9 + (t & 3)] : 0.f;
        }
        __syncthreads();

        if (t < 192) {
            // ------------- w00: float4 streaming, 12 quads/row -------------
            const int r = t / 12;
            const int q = t % 12;
            const int z = z0 + r;
            if (z < Z) {
                const float4* __restrict__ w4 =
                    (const float4*)W + (size_t)z * (WPR / 4) + q;
                const float* xr = x1s + r * NS;

                float s0 = 0.f, s1 = 0.f, s2 = 0.f, s3 = 0.f;
                #pragma unroll
                for (int u = 0; u < NS; u++) {
                    float4 w  = __ldcs(&w4[u * (NS / 4)]);
                    float  xv = xr[u];
                    s0 = fmaf(xv, w.x, s0);
                    s1 = fmaf(xv, w.y, s1);
                    s2 = fmaf(xv, w.z, s2);
                    s3 = fmaf(xv, w.w, s3);
                }
                const float c = NORM * x2s[r * 4 + 0];
                float2* o2 = (float2*)(out + (size_t)z * OPR + 4 * q);
                __stcs(&o2[0], make_float2(c * s0, c * s1));
                __stcs(&o2[1], make_float2(c * s2, c * s3));
            }
        } else if (t < 192 + RPB * 5) {
            // ------------- w01: float2 streaming, 5 pairs/row -------------
            const int u5 = t - 192;
            const int r  = u5 / 5;
            const int p  = u5 % 5;
            const int z  = z0 + r;
            if (z < Z) {
                const float2* __restrict__ w2 =
                    (const float2*)W + (size_t)z * (WPR / 2) + (NS * NS / 2) + p;
                const float* xr = x1s + r * NS;

                float s0 = 0.f, s1 = 0.f;
                #pragma unroll
                for (int u = 0; u < NS; u++) {
                    float2 w  = __ldcs(&w2[u * (NV / 2)]);
                    float  xv = xr[u];
                    s0 = fmaf(xv, w.x, s0);
                    s1 = fmaf(xv, w.y, s1);
                }
                s0 *= NORM;
                s1 *= NORM;
                const float a = x2s[r * 4 + 1];
                const float b = x2s[r * 4 + 2];
                const float c = x2s[r * 4 + 3];
                float2* o2 = (float2*)(out + (size_t)z * OPR + NS + 6 * p);
                __stcs(&o2[0], make_float2(s0 * a, s0 * b));
                __stcs(&o2[1], make_float2(s0 * c, s1 * a));
                __stcs(&o2[2], make_float2(s1 * b, s1 * c));
            }
        }
        __syncthreads();   // protect smem before next tile's staging
    }
}

extern "C" void kernel_launch(void* const* d_in, const int* in_sizes, int n_in,
                              void* d_out, int out_size)
{
    const float* x1 = (const float*)d_in[0];
    const float* x2 = (const float*)d_in[1];
    const float* W  = (const float*)d_in[2];
    float* out = (float*)d_out;

    const int Z = in_sizes[0] / NS;
    const int ntiles = (Z + RPB - 1) / RPB;
    const int blocks = ntiles < PERSISTENT_BLOCKS ? ntiles : PERSISTENT_BLOCKS;
    tpfirst_kernel<<<blocks, TPB>>>(x1, x2, W, out, Z, ntiles);
}

// round 14
// speedup vs baseline: 1.2434x; 1.2434x over previous
#include <cuda_runtime.h>

// Per row z (Z=200000):
//   out[0:48]      = NORM * x2[z,0]   * (x1[z,:] @ w00)   w00 = weights[z,:2304] as 48x48
//   out[48+6p+...] = NORM * x2[z,1+j] * (x1[z,:] @ w01)   w01 = weights[z,2304:] as 48x10
// NORM = 1/sqrt(48).
//
// R9 = R4 (best measured: ncu 332.5us, DRAM 88.4%) with float4 x1 staging:
// block's x1 region (16 rows * 48 floats) is contiguous -> 192 LDG.128
// instead of 768 LDG.32 for the pre-barrier staging phase.

#define NS   48
#define NV   10
#define WPR  2784
#define OPR  78
#define NORM 0.14433756729740643f

#define RPB  16
#define TPB  288

__global__ __launch_bounds__(TPB, 6)
void tpfirst_kernel(const float* __restrict__ x1,
                    const float* __restrict__ x2,
                    const float* __restrict__ W,
                    float* __restrict__ out,
                    int Z)
{
    __shared__ float x1s[RPB * NS];     // 768 floats, contiguous image of x1[z0:z0+16]
    __shared__ float x2s[RPB * 4];

    const int t  = threadIdx.x;
    const int z0 = blockIdx.x * RPB;

    // ---- staging: x1 block region is contiguous -> float4 vectorized ----
    if (z0 + RPB <= Z) {
        const float4* __restrict__ src = (const float4*)(x1 + (size_t)z0 * NS);
        float4* dst = (float4*)x1s;
        #pragma unroll
        for (int i = t; i < RPB * NS / 4; i += TPB)        // 192 float4
            dst[i] = __ldcs(&src[i]);
    } else {
        for (int i = t; i < RPB * NS; i += TPB) {
            int zz = z0 + i / NS;
            x1s[i] = (zz < Z) ? x1[(size_t)zz * NS + (i % NS)] : 0.f;
        }
    }
    if (t < RPB * 4) {
        int zz = z0 + (t >> 2);
        x2s[t] = (zz < Z) ? __ldcs(&x2[(size_t)zz * 9 + (t & 3)]) : 0.f;
    }
    __syncthreads();

    if (t < 192) {
        // ---------------- w00: float4 streaming, 12 quads/row ----------------
        const int r = t / 12;
        const int q = t % 12;
        const int z = z0 + r;
        if (z >= Z) return;

        const float4* __restrict__ w4 =
            (const float4*)W + (size_t)z * (WPR / 4) + q;
        const float* xr = x1s + r * NS;

        float s0 = 0.f, s1 = 0.f, s2 = 0.f, s3 = 0.f;
        #pragma unroll
        for (int u = 0; u < NS; u++) {
            float4 w  = __ldcs(&w4[u * (NS / 4)]);
            float  xv = xr[u];
            s0 = fmaf(xv, w.x, s0);
            s1 = fmaf(xv, w.y, s1);
            s2 = fmaf(xv, w.z, s2);
            s3 = fmaf(xv, w.w, s3);
        }
        const float c = NORM * x2s[r * 4 + 0];
        float2* o2 = (float2*)(out + (size_t)z * OPR + 4 * q);
        __stcs(&o2[0], make_float2(c * s0, c * s1));
        __stcs(&o2[1], make_float2(c * s2, c * s3));
    } else if (t < 192 + RPB * 5) {
        // ---------------- w01: float2 streaming, 5 pairs/row ----------------
        const int u5 = t - 192;
        const int r  = u5 / 5;
        const int p  = u5 % 5;
        const int z  = z0 + r;
        if (z >= Z) return;

        const float2* __restrict__ w2 =
            (const float2*)W + (size_t)z * (WPR / 2) + (NS * NS / 2) + p;
        const float* xr = x1s + r * NS;

        float s0 = 0.f, s1 = 0.f;
        #pragma unroll
        for (int u = 0; u < NS; u++) {
            float2 w  = __ldcs(&w2[u * (NV / 2)]);
            float  xv = xr[u];
            s0 = fmaf(xv, w.x, s0);
            s1 = fmaf(xv, w.y, s1);
        }
        s0 *= NORM;
        s1 *= NORM;
        const float a = x2s[r * 4 + 1];
        const float b = x2s[r * 4 + 2];
        const float c = x2s[r * 4 + 3];
        float2* o2 = (float2*)(out + (size_t)z * OPR + NS + 6 * p);
        __stcs(&o2[0], make_float2(s0 * a, s0 * b));
        __stcs(&o2[1], make_float2(s0 * c, s1 * a));
        __stcs(&o2[2], make_float2(s1 * b, s1 * c));
    }
}

extern "C" void kernel_launch(void* const* d_in, const int* in_sizes, int n_in,
                              void* d_out, int out_size)
{
    const float* x1 = (const float*)d_in[0];
    const float* x2 = (const float*)d_in[1];
    const float* W  = (const float*)d_in[2];
    float* out = (float*)d_out;

    const int Z = in_sizes[0] / NS;
    const int blocks = (Z + RPB - 1) / RPB;
    tpfirst_kernel<<<blocks, TPB>>>(x1, x2, W, out, Z);
}